// round 10
// baseline (speedup 1.0000x reference)
#include <cuda_runtime.h>
#include <cstdint>

#define H_HEADS 8
#define D_IN 64
#define D_H 32
#define B_SZ 32
#define N_NODES 512
#define ST 33                      /* hsm row stride (floats) */

typedef unsigned long long ull;

// Scratch
__device__ float g_h[H_HEADS * B_SZ * N_NODES * D_H];   // per-head msgs, 16 MB
__device__ float g_xt[B_SZ * D_IN * N_NODES];           // x^T [b][d][n], 4 MB

__device__ __forceinline__ ull pack2(float x) {
    ull r; asm("mov.b64 %0, {%1, %1};" : "=l"(r) : "f"(x)); return r;
}
__device__ __forceinline__ void ffma2(ull& acc, ull a, ull b) {
    asm("fma.rn.f32x2 %0, %1, %2, %0;" : "+l"(acc) : "l"(a), "l"(b));
}
__device__ __forceinline__ float lo32(ull v) {
    return __uint_as_float((unsigned)(v & 0xffffffffull));
}
__device__ __forceinline__ float hi32(ull v) {
    return __uint_as_float((unsigned)(v >> 32));
}
__device__ __forceinline__ float ex2f(float t) {
    float p; asm("ex2.approx.f32 %0, %1;" : "=f"(p) : "f"(t)); return p;
}
__device__ __forceinline__ unsigned flipf(float x) {
    unsigned u = __float_as_uint(x);
    unsigned mask = (unsigned)((int)u >> 31) | 0x80000000u;
    return u ^ mask;
}
__device__ __forceinline__ float unflipf(unsigned u) {
    unsigned mask = (u & 0x80000000u) ? 0x80000000u : 0xffffffffu;
    return __uint_as_float(u ^ mask);
}

#define L2E 1.4426950408889634f
#define C02 0.28853900817779268f   /* 0.2 * log2(e) */

// ---------------------------------------------------------------------------
// Kernel 0: transpose inputs -> g_xt[b][d][n]
// grid = B*4 (128-row tiles), 256 threads
// ---------------------------------------------------------------------------
__global__ void __launch_bounds__(256) xt_kernel(const float* __restrict__ inputs) {
    __shared__ float tile[D_IN * 132];
    const int b = blockIdx.x >> 2;
    const int n0 = (blockIdx.x & 3) * 128;

    const float4* src = (const float4*)(inputs + ((size_t)b * N_NODES + n0) * D_IN);
    for (int i = threadIdx.x; i < 128 * 16; i += 256) {
        int r = i >> 4, d4 = (i & 15) * 4;
        float4 v = src[i];
        tile[(d4 + 0) * 132 + r] = v.x;
        tile[(d4 + 1) * 132 + r] = v.y;
        tile[(d4 + 2) * 132 + r] = v.z;
        tile[(d4 + 3) * 132 + r] = v.w;
    }
    __syncthreads();
    for (int i = threadIdx.x; i < D_IN * 32; i += 256) {
        int d = i >> 5, nq = i & 31;
        float4 v;
        v.x = tile[d * 132 + nq * 4 + 0];
        v.y = tile[d * 132 + nq * 4 + 1];
        v.z = tile[d * 132 + nq * 4 + 2];
        v.w = tile[d * 132 + nq * 4 + 3];
        ((float4*)(g_xt + ((size_t)(b * D_IN + d)) * N_NODES + n0))[nq] = v;
    }
}

// ---------------------------------------------------------------------------
// Kernel 1: fused projection + attention for one (h,b) pair.
//   GEMM: h = x^T-chunks (smem) x W (smem), 8 rows x 8 cols / thread.
//   Attention: branch-factorized softmax
//     p_ij = exp(lrelu(et_i+es_j)) = u_i*v_j (s>0) | u2_i*v2_j (s<0)
//   via single sort of j by es_j, 16-granular prefix chunks, per-thread
//   binary searches, per-row <=15-element partials. No serial sweep.
// grid = H*B = 256 blocks, 256 threads, 92160 B smem -> 2 CTA/SM.
// Writes per-head msgs to g_h[hb].
// ---------------------------------------------------------------------------
__global__ void __launch_bounds__(256, 2) att_kernel(const float* __restrict__ linear,
                                                     const float* __restrict__ att_src,
                                                     const float* __restrict__ att_tar) {
    extern __shared__ float smem[];
    float* hsm = smem;                         // 512*33 = 16896
    float* uni = smem + N_NODES * ST;
    // GEMM view of union:
    float* xseg = uni;                         // 8*512 = 4096
    float* Wsm  = uni + 4096;                  // 2048
    // ATT view of union:
    ull*   keys = (ull*)uni;                   // 512 ull (1024 f)
    float* esrc = uni + 1024;                  // 512
    float* etar = uni + 1536;                  // 512
    float* vs   = uni + 2048;                  // 512
    float* v2s  = uni + 2560;                  // 512
    int*   tarr = (int*)(uni + 3072);          // 512
    float* Lc1  = uni + 3584;                  // 33*32
    float* Lc2  = uni + 4640;                  // 33*32
    float* cv1  = uni + 5696;                  // 33
    float* cv2  = uni + 5729;                  // 33

    const int hb = blockIdx.x;
    const int h = hb >> 5;
    const int b = hb & 31;
    const int tid = threadIdx.x;
    const int wid = tid >> 5;
    const int lane = tid & 31;

    float* gslice = g_h + (size_t)hb * N_NODES * D_H;

    // ================= GEMM phase =================
    {
        const int rg = tid >> 2;          // 0..63 -> rows rg*8..rg*8+7
        const int k8 = (tid & 3) * 8;     // col base

        // load W [64][32]
        {
            const float4* W4 = (const float4*)(linear + h * D_IN * D_H);
            float4* Ws4 = (float4*)Wsm;
            for (int i = tid; i < D_IN * D_H / 4; i += 256) Ws4[i] = W4[i];
        }

        ull acc[8][4];
#pragma unroll
        for (int rr = 0; rr < 8; rr++)
#pragma unroll
            for (int q = 0; q < 4; q++) acc[rr][q] = 0ull;

        for (int ch = 0; ch < 8; ch++) {
            __syncthreads();
            const float4* xsrc = (const float4*)(g_xt +
                                 ((size_t)(b * D_IN + ch * 8)) * N_NODES);
            float4* xd = (float4*)xseg;
            for (int i = tid; i < 1024; i += 256) xd[i] = xsrc[i];
            __syncthreads();
#pragma unroll
            for (int dd = 0; dd < 8; dd++) {
                float4 xa = *(const float4*)&xseg[dd * 512 + rg * 8];
                float4 xb = *(const float4*)&xseg[dd * 512 + rg * 8 + 4];
                const ulonglong2* wr =
                    (const ulonglong2*)&Wsm[(ch * 8 + dd) * D_H + k8];
                ulonglong2 w0 = wr[0];
                ulonglong2 w1 = wr[1];
                float xs[8] = {xa.x, xa.y, xa.z, xa.w, xb.x, xb.y, xb.z, xb.w};
#pragma unroll
                for (int rr = 0; rr < 8; rr++) {
                    ull x2 = pack2(xs[rr]);
                    ffma2(acc[rr][0], w0.x, x2);
                    ffma2(acc[rr][1], w0.y, x2);
                    ffma2(acc[rr][2], w1.x, x2);
                    ffma2(acc[rr][3], w1.y, x2);
                }
            }
        }
        __syncthreads();
        // write hsm with per-thread column rotation (bank spread)
#pragma unroll
        for (int rr = 0; rr < 8; rr++) {
            int base = (rg * 8 + rr) * ST + k8;
#pragma unroll
            for (int c = 0; c < 8; c++) {
                int cc = (c + rg) & 7;
                float v = (cc & 1) ? hi32(acc[rr][cc >> 1]) : lo32(acc[rr][cc >> 1]);
                hsm[base + cc] = v;
            }
        }
        __syncthreads();
    }

    // ================= esrc / etar =================
    {
        const float as = att_src[h * D_H + lane];
        const float at = att_tar[h * D_H + lane];
        for (int j = wid; j < N_NODES; j += 8) {
            float v = hsm[j * ST + lane];
            float s1 = v * as;
            float s2 = v * at;
#pragma unroll
            for (int off = 16; off; off >>= 1) {
                s1 += __shfl_xor_sync(0xffffffffu, s1, off);
                s2 += __shfl_xor_sync(0xffffffffu, s2, off);
            }
            if (lane == 0) { esrc[j] = s1; etar[j] = s2; }
        }
    }
    __syncthreads();

    // ================= sort keys by es (asc) =================
    for (int i = tid; i < N_NODES; i += 256)
        keys[i] = ((ull)flipf(esrc[i]) << 32) | (unsigned)i;
    for (int k2 = 2; k2 <= N_NODES; k2 <<= 1) {
        for (int j2 = k2 >> 1; j2 > 0; j2 >>= 1) {
            __syncthreads();
            for (int i = tid; i < N_NODES; i += 256) {
                int ixj = i ^ j2;
                if (ixj > i) {
                    ull a = keys[i], bb = keys[ixj];
                    if ((a > bb) == ((i & k2) == 0)) { keys[i] = bb; keys[ixj] = a; }
                }
            }
        }
    }
    __syncthreads();

    // ========== vs/v2s + per-thread binary searches (2 rows) ==========
    for (int t = tid; t < N_NODES; t += 256) {
        float e = unflipf((unsigned)(keys[t] >> 32));
        vs[t]  = ex2f(e * L2E);
        v2s[t] = ex2f(e * C02);
    }
#pragma unroll
    for (int rr = 0; rr < 2; rr++) {
        int i = tid + rr * 256;
        ull target = ((ull)flipf(-etar[i])) << 32;
        int lo = 0, hi = N_NODES;
#pragma unroll
        for (int it = 0; it < 9; it++) {
            int mid = (lo + hi) >> 1;
            if (keys[mid] < target) lo = mid + 1; else hi = mid;
        }
        tarr[i] = lo;
    }
    __syncthreads();

    // ========== chunk partial sums (32 chunks of 16) ==========
    for (int c = wid; c < 32; c += 8) {
        float l1 = 0.f, l2 = 0.f;
#pragma unroll 4
        for (int tt = 0; tt < 16; tt++) {
            int t = c * 16 + tt;
            int j = (int)(unsigned)(keys[t] & 0xffffffffull);
            float x = hsm[j * ST + lane];
            l1 = fmaf(vs[t], x, l1);
            l2 = fmaf(v2s[t], x, l2);
        }
        Lc1[c * 32 + lane] = l1;
        Lc2[c * 32 + lane] = l2;
        // scalar chunk sums: half-warp reductions
        float sv = (lane < 16) ? vs[c * 16 + lane] : v2s[c * 16 + (lane - 16)];
#pragma unroll
        for (int off = 8; off; off >>= 1)
            sv += __shfl_xor_sync(0xffffffffu, sv, off);
        if (lane == 0) cv1[c] = sv;
        if (lane == 16) cv2[c] = sv;
    }
    __syncthreads();

    // ========== exclusive scans over chunks ==========
    if (wid == 0) {
        float run = 0.f;
#pragma unroll
        for (int c = 0; c < 32; c++) {
            float t = Lc1[c * 32 + lane]; Lc1[c * 32 + lane] = run; run += t;
        }
        Lc1[32 * 32 + lane] = run;
    } else if (wid == 1) {
        float run = 0.f;
#pragma unroll
        for (int c = 0; c < 32; c++) {
            float t = Lc2[c * 32 + lane]; Lc2[c * 32 + lane] = run; run += t;
        }
        Lc2[32 * 32 + lane] = run;
    } else if (wid == 2) {
        float x = cv1[lane];
        float inc = x;
#pragma unroll
        for (int off = 1; off < 32; off <<= 1) {
            float y = __shfl_up_sync(0xffffffffu, inc, off);
            if (lane >= off) inc += y;
        }
        cv1[lane] = inc - x;
        if (lane == 31) cv1[32] = inc;
    } else if (wid == 3) {
        float x = cv2[lane];
        float inc = x;
#pragma unroll
        for (int off = 1; off < 32; off <<= 1) {
            float y = __shfl_up_sync(0xffffffffu, inc, off);
            if (lane >= off) inc += y;
        }
        cv2[lane] = inc - x;
        if (lane == 31) cv2[32] = inc;
    }
    __syncthreads();

    // ========== per-row combine: warp w -> rows [64w, 64w+64) ==========
    {
        const float Tv1 = cv1[32];
        const float T1k = Lc1[32 * 32 + lane];
        for (int r = 0; r < 64; r++) {
            const int i = wid * 64 + r;
            const int t = tarr[i];
            const int c = t >> 4;
            float S1 = Lc1[c * 32 + lane];
            float S2 = Lc2[c * 32 + lane];
            float Sv1 = cv1[c];
            float Sv2 = cv2[c];
            const int t0 = c << 4;
#pragma unroll 4
            for (int tp = t0; tp < t; tp++) {
                int j = (int)(unsigned)(keys[tp] & 0xffffffffull);
                float x = hsm[j * ST + lane];
                float a = vs[tp], b2 = v2s[tp];
                S1 = fmaf(a, x, S1);
                S2 = fmaf(b2, x, S2);
                Sv1 += a; Sv2 += b2;
            }
            float et = etar[i];
            float es = esrc[i];
            float u  = ex2f(et * L2E);
            float u2 = ex2f(et * C02);
            float s = et + es;
            float ps = ex2f(fmaf(fmaxf(s, 0.f), L2E, fminf(s, 0.f) * C02));
            float denom = u * (Tv1 - Sv1) + u2 * Sv2 - ps;
            float sc = 1.f / denom;
            float hx = hsm[i * ST + lane];
            gslice[i * D_H + lane] = (u * (T1k - S1) + u2 * S2 - ps * hx) * sc;
        }
    }
}

// ---------------------------------------------------------------------------
// Kernel 3: msgs = tanh(mean_h(head_msgs) + bias); GRU gated update -> out
// grid = B * 8 (64-row chunks), 256 threads
// ---------------------------------------------------------------------------
__global__ void gru_kernel(const float* __restrict__ inputs,
                           const float* __restrict__ hidden,
                           const float* __restrict__ bias,
                           const float* __restrict__ W_hr,
                           const float* __restrict__ W_hi,
                           const float* __restrict__ W_hm,
                           const float* __restrict__ W_ir,
                           const float* __restrict__ b_ir,
                           const float* __restrict__ W_ii,
                           const float* __restrict__ b_ii,
                           const float* __restrict__ W_in,
                           const float* __restrict__ b_in,
                           float* __restrict__ out) {
    extern __shared__ float smem[];
    float* Wir = smem;                    // 2048
    float* Wii = Wir + D_IN * D_H;        // 2048
    float* Win = Wii + D_IN * D_H;        // 2048
    float* Whr = Win + D_IN * D_H;        // 1024
    float* Whi = Whr + D_H * D_H;         // 1024
    float* Whm = Whi + D_H * D_H;         // 1024
    float* xsm = Whm + D_H * D_H;         // 64*64
    float* msm = xsm + 64 * D_IN;         // 64*32

    const int b = blockIdx.x >> 3;
    const int n0 = (blockIdx.x & 7) * 64;

    for (int i = threadIdx.x; i < D_IN * D_H; i += 256) {
        Wir[i] = W_ir[i]; Wii[i] = W_ii[i]; Win[i] = W_in[i];
    }
    for (int i = threadIdx.x; i < D_H * D_H; i += 256) {
        Whr[i] = W_hr[i]; Whi[i] = W_hi[i]; Whm[i] = W_hm[i];
    }
    for (int i = threadIdx.x; i < 64 * D_IN / 4; i += 256)
        ((float4*)xsm)[i] =
            ((const float4*)(inputs + ((size_t)b * N_NODES + n0) * D_IN))[i];

    for (int i = threadIdx.x; i < 64 * D_H / 4; i += 256) {
        float4 acc = make_float4(0.f, 0.f, 0.f, 0.f);
#pragma unroll
        for (int h = 0; h < H_HEADS; h++) {
            const float4* src = (const float4*)(g_h +
                ((size_t)(h * B_SZ + b) * N_NODES + n0) * D_H);
            float4 v = src[i];
            acc.x += v.x; acc.y += v.y; acc.z += v.z; acc.w += v.w;
        }
        int k4 = (i & 7) * 4;
        float4 r;
        r.x = tanhf(acc.x * 0.125f + bias[k4 + 0]);
        r.y = tanhf(acc.y * 0.125f + bias[k4 + 1]);
        r.z = tanhf(acc.z * 0.125f + bias[k4 + 2]);
        r.w = tanhf(acc.w * 0.125f + bias[k4 + 3]);
        ((float4*)msm)[i] = r;
    }
    __syncthreads();

    const int k = threadIdx.x & 31;
    const int r0 = threadIdx.x >> 5;

    for (int e = 0; e < 8; e++) {
        const int r = r0 + 8 * e;
        float xr = b_ir[k], xi = b_ii[k], xn = b_in[k];
#pragma unroll 8
        for (int d = 0; d < D_IN; d++) {
            float x = xsm[r * D_IN + d];
            xr = fmaf(x, Wir[d * D_H + k], xr);
            xi = fmaf(x, Wii[d * D_H + k], xi);
            xn = fmaf(x, Win[d * D_H + k], xn);
        }
        float hr = 0.f, hi = 0.f, hm = 0.f;
#pragma unroll 8
        for (int d = 0; d < D_H; d++) {
            float mm = msm[r * D_H + d];
            hr = fmaf(mm, Whr[d * D_H + k], hr);
            hi = fmaf(mm, Whi[d * D_H + k], hi);
            hm = fmaf(mm, Whm[d * D_H + k], hm);
        }
        float mg = 1.f / (1.f + __expf(-(xr + hr)));
        float ig = 1.f / (1.f + __expf(-(xi + hi)));
        float nn = tanhf(xn + mg * hm);
        const size_t idx = ((size_t)b * N_NODES + n0 + r) * D_H + k;
        out[idx] = ig * nn + (1.f - ig) * hidden[idx];
    }
}

// ---------------------------------------------------------------------------
// Launch
// ---------------------------------------------------------------------------
extern "C" void kernel_launch(void* const* d_in, const int* in_sizes, int n_in,
                              void* d_out, int out_size) {
    const float* inputs  = (const float*)d_in[0];
    const float* hidden  = (const float*)d_in[1];
    const float* linear  = (const float*)d_in[2];
    const float* bias    = (const float*)d_in[3];
    const float* att_src = (const float*)d_in[4];
    const float* att_tar = (const float*)d_in[5];
    const float* W_hr    = (const float*)d_in[6];
    const float* W_hi    = (const float*)d_in[7];
    const float* W_hm    = (const float*)d_in[8];
    const float* W_ir    = (const float*)d_in[9];
    const float* b_ir    = (const float*)d_in[10];
    const float* W_ii    = (const float*)d_in[11];
    const float* b_ii    = (const float*)d_in[12];
    const float* W_in    = (const float*)d_in[13];
    const float* b_in    = (const float*)d_in[14];
    float* out = (float*)d_out;

    const int att_smem = (N_NODES * ST + 6144) * sizeof(float);   // 92160
    const int gru_smem = (3 * D_IN * D_H + 3 * D_H * D_H + 64 * D_IN + 64 * D_H)
                         * sizeof(float);                          // 61440

    static bool attr_done = false;
    if (!attr_done) {
        cudaFuncSetAttribute(att_kernel, cudaFuncAttributeMaxDynamicSharedMemorySize,
                             att_smem);
        cudaFuncSetAttribute(gru_kernel, cudaFuncAttributeMaxDynamicSharedMemorySize,
                             gru_smem);
        attr_done = true;
    }

    xt_kernel<<<B_SZ * 4, 256>>>(inputs);
    att_kernel<<<H_HEADS * B_SZ, 256, att_smem>>>(linear, att_src, att_tar);
    gru_kernel<<<B_SZ * 8, 256, gru_smem>>>(inputs, hidden, bias,
                                            W_hr, W_hi, W_hm,
                                            W_ir, b_ir, W_ii, b_ii, W_in, b_in,
                                            out);
}